// round 11
// baseline (speedup 1.0000x reference)
#include <cuda_runtime.h>

// PrevEmbedding fused, warp-per-row, balanced single wave:
//   out[row,:] = LN(gathered_row)*g+b + LN(pos_emb[t]+type_emb[ty])*eg+eb
// - LN only the 2048 gathered rows, never the 32000x768 table
// - 1 warp = 1 row: 6 float4 per lane (MLP=6), shuffle-only reduction
// - TPB=448 (14 warps), grid=147 -> 1 CTA/SM across the whole chip, 1 row/warp
// - params staged to smem by ALL threads; epilogue reads via LDS (no L1tex queue)
// - streaming output stores

#define HD     768
#define V4     (HD / 4)     // 192 float4 per row
#define TPB    448
#define NW     (TPB / 32)   // 14 warps = 14 rows per CTA
#define NPAR   (6 * V4)     // 1152 staged float4s
#define LN_EPS 1e-5f

__device__ __forceinline__ void stcs4(float4* p, float4 v) {
    asm volatile("st.global.cs.v4.f32 [%0], {%1,%2,%3,%4};"
                 :: "l"(p), "f"(v.x), "f"(v.y), "f"(v.z), "f"(v.w) : "memory");
}

__global__ __launch_bounds__(TPB)
void prev_embedding_kernel(
    const float* __restrict__ cv,        // [V, H]
    const float* __restrict__ ocr,       // [B, N, H]
    const int*   __restrict__ raw,       // [B*T] int32 view (maybe int64 data)
    const float* __restrict__ cv_g,
    const float* __restrict__ cv_b,
    const float* __restrict__ ocr_g,
    const float* __restrict__ ocr_b,
    const float* __restrict__ pos_emb,   // [T, H]
    const float* __restrict__ type_emb,  // [2, H]
    const float* __restrict__ emb_g,
    const float* __restrict__ emb_b,
    float* __restrict__ out,             // [B*T, H]
    int V, int N, int T, int BT)
{
    // smem layout: [cv_g | cv_b | ocr_g | ocr_b | emb_g | emb_b], each V4 float4s
    __shared__ float4 s_par[NPAR];

    const int tid  = threadIdx.x;
    const int wid  = tid >> 5;
    const int lane = tid & 31;
    const int row  = blockIdx.x * NW + wid;
    const bool active = (row < BT);

    // Stage all 6 param vectors, spread across ALL threads (3 loads max each).
    {
        const float* srcs[6] = { cv_g, cv_b, ocr_g, ocr_b, emb_g, emb_b };
        #pragma unroll
        for (int i = tid; i < NPAR; i += TPB) {
            const int a = i / V4;
            const int e = i - a * V4;
            s_par[i] = ((const float4*)srcs[a])[e];
        }
    }

    float4 x[6], p[6];
    float mu_x, rx, mu_p, rp;
    bool use_ocr = false;
    int t = 0;

    if (active) {
        // id dtype detection: int64 viewed as int32 has zero odd high words.
        // Probes are uniform (L1 broadcast); single id load with selected addr.
        const bool is64 = ((raw[1] | raw[3] | raw[5] | raw[7]) == 0);
        const int  id   = is64 ? raw[2 * row] : raw[row];

        const int b = row / T;
        t = row - b * T;

        const int type_id = (t >= V) ? 1 : 0;  // faithful to reference (0 here)
        const float4* pe4 = (const float4*)(pos_emb + t * HD);
        const float4* te4 = (const float4*)(type_emb + type_id * HD);

        // pos/type loads are id-independent: issue them while id is in flight.
        #pragma unroll
        for (int j = 0; j < 6; j++) {
            float4 a = pe4[lane + 32 * j];
            float4 c = te4[lane + 32 * j];
            p[j] = make_float4(a.x + c.x, a.y + c.y, a.z + c.z, a.w + c.w);
        }

        const float* src;
        use_ocr = (id >= V);
        if (use_ocr) {
            int oi = id - V;
            if (oi > N - 1) oi = N - 1;
            src = ocr + ((long long)b * N + oi) * HD;
        } else {
            int ci = id < 0 ? 0 : (id > V - 1 ? V - 1 : id);
            src = cv + (long long)ci * HD;
        }
        const float4* s4 = (const float4*)src;

        // 6 independent gather loads (MLP=6) as soon as id lands.
        #pragma unroll
        for (int j = 0; j < 6; j++) x[j] = s4[lane + 32 * j];

        float sx = 0.f, sxx = 0.f, sp = 0.f, spp = 0.f;
        #pragma unroll
        for (int j = 0; j < 6; j++) {
            sp  += p[j].x + p[j].y + p[j].z + p[j].w;
            spp += p[j].x*p[j].x + p[j].y*p[j].y + p[j].z*p[j].z + p[j].w*p[j].w;
        }
        #pragma unroll
        for (int j = 0; j < 6; j++) {
            sx  += x[j].x + x[j].y + x[j].z + x[j].w;
            sxx += x[j].x*x[j].x + x[j].y*x[j].y + x[j].z*x[j].z + x[j].w*x[j].w;
        }

        #pragma unroll
        for (int off = 16; off > 0; off >>= 1) {
            sx  += __shfl_xor_sync(0xFFFFFFFFu, sx,  off);
            sxx += __shfl_xor_sync(0xFFFFFFFFu, sxx, off);
            sp  += __shfl_xor_sync(0xFFFFFFFFu, sp,  off);
            spp += __shfl_xor_sync(0xFFFFFFFFu, spp, off);
        }

        const float inv_h = 1.0f / (float)HD;
        mu_x = sx * inv_h;
        rx   = rsqrtf(fmaxf(sxx * inv_h - mu_x * mu_x, 0.f) + LN_EPS);
        mu_p = sp * inv_h;
        rp   = rsqrtf(fmaxf(spp * inv_h - mu_p * mu_p, 0.f) + LN_EPS);
    }

    __syncthreads();   // staged params visible

    if (active) {
        const float4* gm = s_par + (use_ocr ? 2 * V4 : 0);
        const float4* bm = gm + V4;
        const float4* eg = s_par + 4 * V4;
        const float4* eb = s_par + 5 * V4;
        float4* o = (float4*)(out + (long long)row * HD);

        #pragma unroll
        for (int j = 0; j < 6; j++) {
            const int h = lane + 32 * j;
            const float4 g  = gm[h];
            const float4 bb = bm[h];
            const float4 g2 = eg[h];
            const float4 b2 = eb[h];
            float4 r;
            r.x = (x[j].x - mu_x) * rx * g.x + bb.x + (p[j].x - mu_p) * rp * g2.x + b2.x;
            r.y = (x[j].y - mu_x) * rx * g.y + bb.y + (p[j].y - mu_p) * rp * g2.y + b2.y;
            r.z = (x[j].z - mu_x) * rx * g.z + bb.z + (p[j].z - mu_p) * rp * g2.z + b2.z;
            r.w = (x[j].w - mu_x) * rx * g.w + bb.w + (p[j].w - mu_p) * rp * g2.w + b2.w;
            stcs4(o + h, r);
        }
    }
}

extern "C" void kernel_launch(void* const* d_in, const int* in_sizes, int n_in,
                              void* d_out, int out_size) {
    const float* cv       = (const float*)d_in[0];   // [V, H]
    const float* ocr      = (const float*)d_in[1];   // [B, N, H]
    const int*   ids_raw  = (const int*)d_in[2];     // [B, T] int32 or int64
    const float* cv_g     = (const float*)d_in[3];
    const float* cv_b     = (const float*)d_in[4];
    const float* ocr_g    = (const float*)d_in[5];
    const float* ocr_b    = (const float*)d_in[6];
    const float* pos_emb  = (const float*)d_in[7];   // [T, H]
    const float* type_emb = (const float*)d_in[8];   // [2, H]
    const float* emb_g    = (const float*)d_in[9];
    const float* emb_b    = (const float*)d_in[10];
    float* out = (float*)d_out;

    const int Hs = in_sizes[3];             // 768
    const int V  = in_sizes[0] / Hs;        // 32000
    const int T  = in_sizes[7] / Hs;        // 128
    const int BT = in_sizes[2];             // 2048
    const int B  = BT / T;                  // 16
    const int N  = in_sizes[1] / (B * Hs);  // 50

    const int grid = (BT + NW - 1) / NW;    // 147
    prev_embedding_kernel<<<grid, TPB>>>(cv, ocr, ids_raw,
                                         cv_g, cv_b, ocr_g, ocr_b,
                                         pos_emb, type_emb, emb_g, emb_b,
                                         out, V, N, T, BT);
}

// round 13
// speedup vs baseline: 1.0608x; 1.0608x over previous
#include <cuda_runtime.h>

// PrevEmbedding fused, 2-warps-per-row (64 lanes x 3 float4):
//   out[row,:] = LN(gathered_row)*g+b + LN(pos_emb[t]+type_emb[ty])*eg+eb
// - LN only the 2048 gathered rows, never the 32000x768 table
// - 64 threads per row -> 4096 warps total -> ~28 warps/SM (2x latency hiding)
// - warp-pair stat combine via named barrier (bar.sync id,64): no CTA-wide sync
// - id candidates (int32/int64 views) loaded in parallel with dtype probes
// - params via L1 (hit after first warp), streaming output stores

#define HD     768
#define TPB    256          // 8 warps = 4 row-pairs per CTA
#define RPC    4            // rows per CTA
#define LN_EPS 1e-5f

__device__ __forceinline__ void stcs4(float4* p, float4 v) {
    asm volatile("st.global.cs.v4.f32 [%0], {%1,%2,%3,%4};"
                 :: "l"(p), "f"(v.x), "f"(v.y), "f"(v.z), "f"(v.w) : "memory");
}

__global__ __launch_bounds__(TPB)
void prev_embedding_kernel(
    const float* __restrict__ cv,        // [V, H]
    const float* __restrict__ ocr,       // [B, N, H]
    const int*   __restrict__ raw,       // [B*T] int32 view (maybe int64 data)
    const float* __restrict__ cv_g,
    const float* __restrict__ cv_b,
    const float* __restrict__ ocr_g,
    const float* __restrict__ ocr_b,
    const float* __restrict__ pos_emb,   // [T, H]
    const float* __restrict__ type_emb,  // [2, H]
    const float* __restrict__ emb_g,
    const float* __restrict__ emb_b,
    float* __restrict__ out,             // [B*T, H]
    int V, int N, int T, int BT)
{
    __shared__ float4 s_red[RPC][2];     // [pair][warpInPair] = {sx,sxx,sp,spp}

    const int tid    = threadIdx.x;
    const int wid    = tid >> 5;
    const int lane   = tid & 31;
    const int pair   = wid >> 1;         // 0..3
    const int wip    = wid & 1;          // warp-in-pair
    const int h0     = wip * 32 + lane;  // 0..63: lane position within the row
    const int row    = blockIdx.x * RPC + pair;
    if (row >= BT) return;

    // --- id fetch: both dtype candidates + probes issued in parallel ---
    const int pr   = raw[1] | raw[3] | raw[5] | raw[7];  // uniform, L1 broadcast
    const int id32 = raw[row];
    const int id64 = raw[2 * row];
    const int id   = (pr == 0) ? id64 : id32;   // int64 view has zero odd words

    const int b = row / T;
    const int t = row - b * T;

    const int type_id = (t >= V) ? 1 : 0;       // faithful to reference (0 here)
    const float4* pe4 = (const float4*)(pos_emb + t * HD);
    const float4* te4 = (const float4*)(type_emb + type_id * HD);

    // pos/type loads are id-independent: in flight during id selection.
    float4 p[3];
    #pragma unroll
    for (int j = 0; j < 3; j++) {
        float4 a = pe4[h0 + 64 * j];
        float4 c = te4[h0 + 64 * j];
        p[j] = make_float4(a.x + c.x, a.y + c.y, a.z + c.z, a.w + c.w);
    }

    const float* src;
    const bool use_ocr = (id >= V);
    if (use_ocr) {
        int oi = id - V;
        if (oi > N - 1) oi = N - 1;
        src = ocr + ((long long)b * N + oi) * HD;
    } else {
        int ci = id < 0 ? 0 : (id > V - 1 ? V - 1 : id);
        src = cv + (long long)ci * HD;
    }
    const float4* s4 = (const float4*)src;

    float4 x[3];
    #pragma unroll
    for (int j = 0; j < 3; j++) x[j] = s4[h0 + 64 * j];

    float sx = 0.f, sxx = 0.f, sp = 0.f, spp = 0.f;
    #pragma unroll
    for (int j = 0; j < 3; j++) {
        sp  += p[j].x + p[j].y + p[j].z + p[j].w;
        spp += p[j].x*p[j].x + p[j].y*p[j].y + p[j].z*p[j].z + p[j].w*p[j].w;
        sx  += x[j].x + x[j].y + x[j].z + x[j].w;
        sxx += x[j].x*x[j].x + x[j].y*x[j].y + x[j].z*x[j].z + x[j].w*x[j].w;
    }

    #pragma unroll
    for (int off = 16; off > 0; off >>= 1) {
        sx  += __shfl_xor_sync(0xFFFFFFFFu, sx,  off);
        sxx += __shfl_xor_sync(0xFFFFFFFFu, sxx, off);
        sp  += __shfl_xor_sync(0xFFFFFFFFu, sp,  off);
        spp += __shfl_xor_sync(0xFFFFFFFFu, spp, off);
    }

    // cross-warp combine within the pair: independent named barrier per pair
    if (lane == 0) s_red[pair][wip] = make_float4(sx, sxx, sp, spp);
    asm volatile("bar.sync %0, 64;" :: "r"(pair) : "memory");
    const float4 r0 = s_red[pair][0];
    const float4 r1 = s_red[pair][1];

    const float inv_h = 1.0f / (float)HD;
    const float mu_x = (r0.x + r1.x) * inv_h;
    const float rx   = rsqrtf(fmaxf((r0.y + r1.y) * inv_h - mu_x * mu_x, 0.f) + LN_EPS);
    const float mu_p = (r0.z + r1.z) * inv_h;
    const float rp   = rsqrtf(fmaxf((r0.w + r1.w) * inv_h - mu_p * mu_p, 0.f) + LN_EPS);

    const float4* gm  = (const float4*)(use_ocr ? ocr_g : cv_g);
    const float4* bm  = (const float4*)(use_ocr ? ocr_b : cv_b);
    const float4* egm = (const float4*)emb_g;
    const float4* ebm = (const float4*)emb_b;
    float4* o = (float4*)(out + (long long)row * HD);

    #pragma unroll
    for (int j = 0; j < 3; j++) {
        const int h = h0 + 64 * j;
        const float4 g  = gm[h];
        const float4 bb = bm[h];
        const float4 eg = egm[h];
        const float4 eb = ebm[h];
        float4 r;
        r.x = (x[j].x - mu_x) * rx * g.x + bb.x + (p[j].x - mu_p) * rp * eg.x + eb.x;
        r.y = (x[j].y - mu_x) * rx * g.y + bb.y + (p[j].y - mu_p) * rp * eg.y + eb.y;
        r.z = (x[j].z - mu_x) * rx * g.z + bb.z + (p[j].z - mu_p) * rp * eg.z + eb.z;
        r.w = (x[j].w - mu_x) * rx * g.w + bb.w + (p[j].w - mu_p) * rp * eg.w + eb.w;
        stcs4(o + h, r);
    }
}

extern "C" void kernel_launch(void* const* d_in, const int* in_sizes, int n_in,
                              void* d_out, int out_size) {
    const float* cv       = (const float*)d_in[0];   // [V, H]
    const float* ocr      = (const float*)d_in[1];   // [B, N, H]
    const int*   ids_raw  = (const int*)d_in[2];     // [B, T] int32 or int64
    const float* cv_g     = (const float*)d_in[3];
    const float* cv_b     = (const float*)d_in[4];
    const float* ocr_g    = (const float*)d_in[5];
    const float* ocr_b    = (const float*)d_in[6];
    const float* pos_emb  = (const float*)d_in[7];   // [T, H]
    const float* type_emb = (const float*)d_in[8];   // [2, H]
    const float* emb_g    = (const float*)d_in[9];
    const float* emb_b    = (const float*)d_in[10];
    float* out = (float*)d_out;

    const int Hs = in_sizes[3];             // 768
    const int V  = in_sizes[0] / Hs;        // 32000
    const int T  = in_sizes[7] / Hs;        // 128
    const int BT = in_sizes[2];             // 2048
    const int B  = BT / T;                  // 16
    const int N  = in_sizes[1] / (B * Hs);  // 50

    const int grid = (BT + RPC - 1) / RPC;  // 512
    prev_embedding_kernel<<<grid, TPB>>>(cv, ocr, ids_raw,
                                         cv_g, cv_b, ocr_g, ocr_b,
                                         pos_emb, type_emb, emb_g, emb_b,
                                         out, V, N, T, BT);
}